// round 14
// baseline (speedup 1.0000x reference)
#include <cuda_runtime.h>
#include <cuda_bf16.h>
#include <cstdint>

#define MAX_CTA 2048
__device__ float g_cta_sum[MAX_CTA];
__device__ int   g_done_ctr = 0;

// ---------------------------------------------------------------------------
// CTA-team kernel: CTA b owns ROWS consecutive rows; for each row, warp j
// processes the j-th contiguous 1/8 slice of the VALID prefix. All warps in
// a CTA do identical per-row work -> no intra-CTA idle warps; per-CTA work is
// a sum of ROWS row-lengths -> 3x tighter spread than warp-per-row.
//   loss = (1/B) * sum_row (1/L) * sum_{t<L} (pred - log(align))^2
// Deterministic: static ownership, fixed accumulation & reduce order.
// ---------------------------------------------------------------------------
template <int BLOCK, int ROWS>
__global__ void __launch_bounds__(BLOCK)
dploss_team_kernel(const float* __restrict__ pred,
                   const float* __restrict__ align,
                   const int* __restrict__ lens,
                   float* __restrict__ out,
                   int C, int B, int nCta) {
    const int lane = threadIdx.x & 31;
    const int wid  = threadIdx.x >> 5;          // slice id 0..7
    const int r0   = blockIdx.x * ROWS;

    // Preload all ROWS lens in one batched round (no per-row dependent stall).
    int Lr[ROWS];
    #pragma unroll
    for (int i = 0; i < ROWS; i++) {
        int r = r0 + i;
        Lr[i] = (r < B) ? __ldg(lens + r) : 0;
    }

    float acc = 0.0f;

    #pragma unroll
    for (int i = 0; i < ROWS; i++) {
        const int L = Lr[i];
        if (L <= 0) continue;
        const int V  = (L + 3) >> 2;            // valid chunks
        const int Vs = (V + 7) >> 3;            // chunks per slice (<=64 @T=2048)
        const int st = wid * Vs;
        const int en = min(st + Vs, V);
        if (st >= en) continue;

        const size_t base = (size_t)(r0 + i) * (size_t)C;
        const float4* __restrict__ p4 = reinterpret_cast<const float4*>(pred) + base;
        const float4* __restrict__ a4 = reinterpret_cast<const float4*>(align) + base;

        float s = 0.0f;

        // Slice is <=64 chunks -> at most 2 chunks per lane; batch both loads.
        const int c0 = st + lane;
        const int c1 = c0 + 32;
        const bool v0 = c0 < en;
        const bool v1 = c1 < en;
        float4 p0, a0, p1, a1;
        if (v0) { p0 = p4[c0]; a0 = a4[c0]; }
        if (v1) { p1 = p4[c1]; a1 = a4[c1]; }

        if (v0) {
            const int rem = L - (c0 << 2);
            float d = p0.x - __logf(a0.x);
            s = fmaf(d, d, s);
            if (rem > 1) { d = p0.y - __logf(a0.y); s = fmaf(d, d, s); }
            if (rem > 2) { d = p0.z - __logf(a0.z); s = fmaf(d, d, s); }
            if (rem > 3) { d = p0.w - __logf(a0.w); s = fmaf(d, d, s); }
        }
        if (v1) {
            const int rem = L - (c1 << 2);
            float d = p1.x - __logf(a1.x);
            s = fmaf(d, d, s);
            if (rem > 1) { d = p1.y - __logf(a1.y); s = fmaf(d, d, s); }
            if (rem > 2) { d = p1.z - __logf(a1.z); s = fmaf(d, d, s); }
            if (rem > 3) { d = p1.w - __logf(a1.w); s = fmaf(d, d, s); }
        }
        // Generality guard (T > 2048 would make Vs > 64): strided tail.
        for (int c = st + lane + 64; c < en; c += 32) {
            float4 p = p4[c];
            float4 a = a4[c];
            const int rem = L - (c << 2);
            float d = p.x - __logf(a.x);
            s = fmaf(d, d, s);
            if (rem > 1) { d = p.y - __logf(a.y); s = fmaf(d, d, s); }
            if (rem > 2) { d = p.z - __logf(a.z); s = fmaf(d, d, s); }
            if (rem > 3) { d = p.w - __logf(a.w); s = fmaf(d, d, s); }
        }

        acc = fmaf(s, __frcp_rn((float)L), acc);   // fixed per-row order
    }

    // Warp reduction (fixed order), then fixed-order CTA reduction.
    #pragma unroll
    for (int off = 16; off > 0; off >>= 1)
        acc += __shfl_down_sync(0xFFFFFFFFu, acc, off);
    __shared__ float s_w[BLOCK / 32];
    if (lane == 0) s_w[wid] = acc;
    __syncthreads();

    __shared__ bool s_is_last;
    if (threadIdx.x == 0) {
        float v = 0.0f;
        #pragma unroll
        for (int k = 0; k < BLOCK / 32; k++) v += s_w[k];
        g_cta_sum[blockIdx.x] = v;
        __threadfence();
        int old = atomicAdd(&g_done_ctr, 1);
        s_is_last = (old == nCta - 1);
    }
    __syncthreads();

    if (s_is_last) {
        float v = 0.0f;
        for (int i = threadIdx.x; i < nCta; i += BLOCK)  // fixed strided order
            v += g_cta_sum[i];
        __shared__ float s_fin[BLOCK / 32];
        #pragma unroll
        for (int off = 16; off > 0; off >>= 1)
            v += __shfl_down_sync(0xFFFFFFFFu, v, off);
        if (lane == 0) s_fin[wid] = v;
        __syncthreads();
        if (threadIdx.x == 0) {
            float t = 0.0f;
            #pragma unroll
            for (int k = 0; k < BLOCK / 32; k++) t += s_fin[k];
            out[0] = t / (float)B;
            g_done_ctr = 0;                     // reset for next graph replay
        }
    }
}

extern "C" void kernel_launch(void* const* d_in, const int* in_sizes, int n_in,
                              void* d_out, int out_size) {
    const float* pred  = (const float*)d_in[0];
    const float* align = (const float*)d_in[1];
    const int*   lens  = (const int*)d_in[2];
    float* out = (float*)d_out;

    const int B = in_sizes[2];
    const int T = in_sizes[0] / B;
    const int C = T >> 2;

    constexpr int BLOCK = 256;                  // 8 warps = 8 slices per row
    constexpr int ROWS  = 8;
    int grid = (B + ROWS - 1) / ROWS;           // 512 CTAs for B=4096
    if (grid > MAX_CTA) grid = MAX_CTA;
    if (grid < 1) grid = 1;

    dploss_team_kernel<BLOCK, ROWS><<<grid, BLOCK>>>(pred, align, lens, out,
                                                     C, B, grid);
}